// round 2
// baseline (speedup 1.0000x reference)
#include <cuda_runtime.h>
#include <math.h>

// Problem constants (fixed by the dataset; scratch sized for them)
#define DIMH   128
#define MAXN   40000
#define MAXE   640000

// ---------------- device scratch (no runtime allocation allowed) ----------------
__device__ float g_K[MAXN * DIMH];
__device__ float g_V[MAXN * DIMH];
__device__ float g_agg[MAXN * DIMH];
__device__ float g_y[MAXN * DIMH];
__device__ float g_z[MAXN * 2 * DIMH];
__device__ float g_escore[MAXE * 8];
__device__ float g_denom[MAXN * 8];
__device__ int   g_ei[2 * MAXE];     // normalized int32 edge indices
__device__ int   g_idx64;            // 1 if input edge_index is int64
__device__ float g_stats[512];   // [0:128) s1_bn1, [128) s2_bn1, [256) s1_bn2, [384) s2_bn2
__device__ float g_aff[512];     // [0:128) scale1, [128) shift1, [256) scale2, [384) shift2

// ---------------- packed fp32x2 helpers (Blackwell) ----------------
__device__ __forceinline__ unsigned long long pack2(float lo, float hi) {
    unsigned long long r;
    asm("mov.b64 %0, {%1, %2};" : "=l"(r) : "f"(lo), "f"(hi));
    return r;
}
__device__ __forceinline__ float2 unpack2(unsigned long long v) {
    float2 f;
    asm("mov.b64 {%0, %1}, %2;" : "=f"(f.x), "=f"(f.y) : "l"(v));
    return f;
}
__device__ __forceinline__ unsigned long long fma2(unsigned long long a,
                                                   unsigned long long b,
                                                   unsigned long long c) {
    unsigned long long d;
    asm("fma.rn.f32x2 %0, %1, %2, %3;" : "=l"(d) : "l"(a), "l"(b), "l"(c));
    return d;
}
__device__ __forceinline__ void red_add_v4(float* p, float4 v) {
    asm volatile("red.global.add.v4.f32 [%0], {%1, %2, %3, %4};"
                 :: "l"(p), "f"(v.x), "f"(v.y), "f"(v.z), "f"(v.w) : "memory");
}

// ---------------- edge_index dtype detection + normalization ----------------
// int64 indices are all < 40000 as u64. int32 data reinterpreted as u64 puts a
// random index in the high 32 bits -> values >= 2^32 with overwhelming probability.
__global__ void detect_idx_kernel(const unsigned long long* p) {
    __shared__ int big;
    if (threadIdx.x == 0) big = 0;
    __syncthreads();
    unsigned long long v = p[threadIdx.x];   // scan first 1024 u64 words (safe: buffer >= 5 MB)
    if (v >= (1ULL << 32)) atomicOr(&big, 1);
    __syncthreads();
    if (threadIdx.x == 0) g_idx64 = big ? 0 : 1;
}

__global__ void convert_idx_kernel(const void* p, int* out, int n) {
    int i = blockIdx.x * blockDim.x + threadIdx.x;
    if (i >= n) return;
    if (g_idx64) out[i] = (int)((const long long*)p)[i];
    else         out[i] = ((const int*)p)[i];
}

// ---------------- init: zero accumulators ----------------
__global__ void init_kernel(float* agg, float* denom, float* stats, int nAgg, int nDen) {
    int i = blockIdx.x * blockDim.x + threadIdx.x;
    if (i < nAgg) agg[i] = 0.f;
    if (i < nDen) denom[i] = 0.f;
    if (i < 512)  stats[i] = 0.f;
}

// ---------------- generic SGEMM: C[M,N] = A[M,K] @ B[N,K]^T + bias (+epilogue) ----------------
// AAFF: apply per-K-column affine to A on load (fused BN-apply)
// RES:  0 none, 1 += res[row,col], 2 += res[row,col]*rscale[col]+rshift[col]
template<bool AAFF, bool RELU, int RES>
__global__ __launch_bounds__(256, 2)
void gemm_kernel(const float* __restrict__ A, int lda,
                 const float* __restrict__ B,
                 const float* __restrict__ bias,
                 const float* __restrict__ ascale, const float* __restrict__ ashift,
                 const float* __restrict__ res,
                 const float* __restrict__ rscale, const float* __restrict__ rshift,
                 float* __restrict__ C, int ldc,
                 int M, int K)
{
    __shared__ __align__(16) float As[32][130];  // k-major, rows of A
    __shared__ __align__(16) float Bs[32][132];  // k-major, rows of B
    const int tid = threadIdx.x;
    const int bm0 = blockIdx.x * 128;
    const int bn0 = blockIdx.y * 128;
    const int tx = tid & 15;     // 16 col groups * 8 cols
    const int ty = tid >> 4;     // 16 row groups * 8 rows

    unsigned long long acc[4][8];  // row-pairs (2 rows packed) x 8 cols
#pragma unroll
    for (int r = 0; r < 4; r++)
#pragma unroll
        for (int c = 0; c < 8; c++) acc[r][c] = 0ULL;

    for (int kk = 0; kk < K; kk += 32) {
        // load A tile (transpose to k-major), guarded on M
#pragma unroll
        for (int i = 0; i < 4; i++) {
            int lin = tid + i * 256;
            int row = lin >> 3;
            int kq = (lin & 7) * 4;
            float4 v = make_float4(0.f, 0.f, 0.f, 0.f);
            int grow = bm0 + row;
            if (grow < M)
                v = *reinterpret_cast<const float4*>(A + (size_t)grow * lda + kk + kq);
            if (AAFF) {
                v.x = v.x * ascale[kk + kq + 0] + ashift[kk + kq + 0];
                v.y = v.y * ascale[kk + kq + 1] + ashift[kk + kq + 1];
                v.z = v.z * ascale[kk + kq + 2] + ashift[kk + kq + 2];
                v.w = v.w * ascale[kk + kq + 3] + ashift[kk + kq + 3];
            }
            As[kq + 0][row] = v.x; As[kq + 1][row] = v.y;
            As[kq + 2][row] = v.z; As[kq + 3][row] = v.w;
        }
        // load B tile (transpose to k-major); N blocks are always full
#pragma unroll
        for (int i = 0; i < 4; i++) {
            int lin = tid + i * 256;
            int row = lin >> 3;
            int kq = (lin & 7) * 4;
            float4 v = *reinterpret_cast<const float4*>(B + (size_t)(bn0 + row) * K + kk + kq);
            Bs[kq + 0][row] = v.x; Bs[kq + 1][row] = v.y;
            Bs[kq + 2][row] = v.z; Bs[kq + 3][row] = v.w;
        }
        __syncthreads();

#pragma unroll 8
        for (int k = 0; k < 32; k++) {
            unsigned long long a2[4];
#pragma unroll
            for (int r = 0; r < 4; r++)
                a2[r] = *reinterpret_cast<const unsigned long long*>(&As[k][ty * 8 + 2 * r]);
            float4 b0 = *reinterpret_cast<const float4*>(&Bs[k][tx * 8]);
            float4 b1 = *reinterpret_cast<const float4*>(&Bs[k][tx * 8 + 4]);
            float bb[8] = {b0.x, b0.y, b0.z, b0.w, b1.x, b1.y, b1.z, b1.w};
#pragma unroll
            for (int c = 0; c < 8; c++) {
                unsigned long long bd = pack2(bb[c], bb[c]);
#pragma unroll
                for (int r = 0; r < 4; r++)
                    acc[r][c] = fma2(a2[r], bd, acc[r][c]);
            }
        }
        __syncthreads();
    }

    // epilogue
    const int col0 = bn0 + tx * 8;
    float bv[8], rs[8], rh[8];
#pragma unroll
    for (int c = 0; c < 8; c++) bv[c] = bias[col0 + c];
    if (RES == 2) {
#pragma unroll
        for (int c = 0; c < 8; c++) { rs[c] = rscale[col0 + c]; rh[c] = rshift[col0 + c]; }
    }
#pragma unroll
    for (int r = 0; r < 4; r++) {
#pragma unroll
        for (int p = 0; p < 2; p++) {
            int row = bm0 + ty * 8 + 2 * r + p;
            if (row >= M) continue;
            float v[8];
#pragma unroll
            for (int c = 0; c < 8; c++) {
                float2 f = unpack2(acc[r][c]);
                v[c] = (p ? f.y : f.x) + bv[c];
            }
            if (RES >= 1) {
                const float4* rp = reinterpret_cast<const float4*>(res + (size_t)row * ldc + col0);
                float4 q0 = rp[0], q1 = rp[1];
                float q[8] = {q0.x, q0.y, q0.z, q0.w, q1.x, q1.y, q1.z, q1.w};
                if (RES == 1) {
#pragma unroll
                    for (int c = 0; c < 8; c++) v[c] += q[c];
                } else {
#pragma unroll
                    for (int c = 0; c < 8; c++) v[c] += q[c] * rs[c] + rh[c];
                }
            }
            if (RELU) {
#pragma unroll
                for (int c = 0; c < 8; c++) v[c] = fmaxf(v[c], 0.f);
            }
            float4 o0 = make_float4(v[0], v[1], v[2], v[3]);
            float4 o1 = make_float4(v[4], v[5], v[6], v[7]);
            *reinterpret_cast<float4*>(C + (size_t)row * ldc + col0)     = o0;
            *reinterpret_cast<float4*>(C + (size_t)row * ldc + col0 + 4) = o1;
        }
    }
}

// ---------------- edge pass A: e = exp(K[src].Q[dst]/4), denom[dst,h] += e ----------------
// (segment-max pass skipped: scores are ~N(0,0.57^2); softmax is shift-invariant)
__global__ void edge_exp_kernel(const float* __restrict__ K, const float* __restrict__ Q,
                                const int* __restrict__ ei,
                                float* __restrict__ escore, float* __restrict__ denom, int E)
{
    int t = blockIdx.x * blockDim.x + threadIdx.x;
    if (t >= E * 8) return;
    int e = t >> 3, h = t & 7;
    int src = ei[e];
    int dst = ei[E + e];
    const float4* kr = reinterpret_cast<const float4*>(K + (size_t)src * DIMH + h * 16);
    const float4* qr = reinterpret_cast<const float4*>(Q + (size_t)dst * DIMH + h * 16);
    float s = 0.f;
#pragma unroll
    for (int i = 0; i < 4; i++) {
        float4 a = kr[i], b = qr[i];
        s += a.x * b.x + a.y * b.y + a.z * b.z + a.w * b.w;
    }
    s *= 0.25f;  // 1/sqrt(16)
    float ev = expf(s);
    escore[t] = ev;
    atomicAdd(&denom[dst * 8 + h], ev);
}

// ---------------- edge pass B: agg[dst] += V[src] * attn ----------------
__global__ void edge_msg_kernel(const float* __restrict__ V,
                                const int* __restrict__ ei,
                                const float* __restrict__ escore,
                                const float* __restrict__ denom,
                                float* __restrict__ agg, int E)
{
    int t = blockIdx.x * blockDim.x + threadIdx.x;
    if (t >= E * 8) return;
    int e = t >> 3, h = t & 7;
    int src = ei[e];
    int dst = ei[E + e];
    float attn = escore[t] / (denom[dst * 8 + h] + 1e-16f);
    const float4* vr = reinterpret_cast<const float4*>(V + (size_t)src * DIMH + h * 16);
    float* op = agg + (size_t)dst * DIMH + h * 16;
#pragma unroll
    for (int i = 0; i < 4; i++) {
        float4 v = vr[i];
        red_add_v4(op + i * 4, make_float4(v.x * attn, v.y * attn, v.z * attn, v.w * attn));
    }
}

// ---------------- batchnorm stats: per-column sum and sum-of-squares ----------------
__global__ void stats_kernel(const float* __restrict__ X, float* s1, float* s2, int M)
{
    __shared__ float sa[256], sb[256];
    int col = threadIdx.x & 127;
    int half = threadIdx.x >> 7;
    int per = (M + gridDim.x - 1) / gridDim.x;
    int r0 = blockIdx.x * per;
    int r1 = min(M, r0 + per);
    float a = 0.f, b = 0.f;
    for (int r = r0 + half; r < r1; r += 2) {
        float v = X[(size_t)r * DIMH + col];
        a += v;
        b = fmaf(v, v, b);
    }
    sa[threadIdx.x] = a; sb[threadIdx.x] = b;
    __syncthreads();
    if (half == 0) {
        atomicAdd(&s1[col], a + sa[col + 128]);
        atomicAdd(&s2[col], b + sb[col + 128]);
    }
}

// ---------------- turn (s1,s2,gamma,beta) into per-column affine ----------------
__global__ void finalize_kernel(const float* __restrict__ stats,
                                const float* __restrict__ g, const float* __restrict__ b,
                                float* scale, float* shift, float invN)
{
    int c = threadIdx.x;
    float mu = stats[c] * invN;
    float var = stats[128 + c] * invN - mu * mu;
    float sc = g[c] * rsqrtf(var + 1e-5f);
    scale[c] = sc;
    shift[c] = b[c] - mu * sc;
}

// ---------------- apply BN2 in place on the output buffer ----------------
__global__ void bn_apply_kernel(float* io, const float* __restrict__ scale,
                                const float* __restrict__ shift, int n4)
{
    int i = blockIdx.x * blockDim.x + threadIdx.x;
    if (i >= n4) return;
    float4 v = reinterpret_cast<float4*>(io)[i];
    int col = (i & 31) * 4;
    v.x = v.x * scale[col + 0] + shift[col + 0];
    v.y = v.y * scale[col + 1] + shift[col + 1];
    v.z = v.z * scale[col + 2] + shift[col + 2];
    v.w = v.w * scale[col + 3] + shift[col + 3];
    reinterpret_cast<float4*>(io)[i] = v;
}

// ---------------- launch ----------------
extern "C" void kernel_launch(void* const* d_in, const int* in_sizes, int n_in,
                              void* d_out, int out_size)
{
    const float* x    = (const float*)d_in[0];
    const void*  eraw = d_in[1];
    const float* Wk   = (const float*)d_in[2];
    const float* bk   = (const float*)d_in[3];
    const float* Wv   = (const float*)d_in[4];
    const float* bv   = (const float*)d_in[5];
    const float* Wo   = (const float*)d_in[6];
    const float* bo   = (const float*)d_in[7];
    const float* bn1g = (const float*)d_in[8];
    const float* bn1b = (const float*)d_in[9];
    const float* W1   = (const float*)d_in[10];
    const float* b1   = (const float*)d_in[11];
    const float* W2   = (const float*)d_in[12];
    const float* b2   = (const float*)d_in[13];
    const float* bn2g = (const float*)d_in[14];
    const float* bn2b = (const float*)d_in[15];
    float* out = (float*)d_out;

    const int M = in_sizes[0] / DIMH;   // 40000
    const int E = in_sizes[1] / 2;      // 640000

    float *pK, *pV, *pAgg, *pY, *pZ, *pEsc, *pDen, *pStats, *pAff;
    int *pEi;
    cudaGetSymbolAddress((void**)&pK,     g_K);
    cudaGetSymbolAddress((void**)&pV,     g_V);
    cudaGetSymbolAddress((void**)&pAgg,   g_agg);
    cudaGetSymbolAddress((void**)&pY,     g_y);
    cudaGetSymbolAddress((void**)&pZ,     g_z);
    cudaGetSymbolAddress((void**)&pEsc,   g_escore);
    cudaGetSymbolAddress((void**)&pDen,   g_denom);
    cudaGetSymbolAddress((void**)&pEi,    g_ei);
    cudaGetSymbolAddress((void**)&pStats, g_stats);
    cudaGetSymbolAddress((void**)&pAff,   g_aff);

    // normalize edge_index dtype (int64 vs int32) into int scratch
    detect_idx_kernel<<<1, 1024>>>((const unsigned long long*)eraw);
    convert_idx_kernel<<<(2 * E + 255) / 256, 256>>>(eraw, pEi, 2 * E);

    const int nAgg = M * DIMH;
    const int initBlocks = (nAgg + 255) / 256;
    init_kernel<<<initBlocks, 256>>>(pAgg, pDen, pStats, nAgg, M * 8);

    dim3 g1((M + 127) / 128, 1);
    dim3 g2((M + 127) / 128, 2);

    // K = x @ Wk^T + bk ; V = x @ Wv^T + bv
    gemm_kernel<false, false, 0><<<g1, 256>>>(x, DIMH, Wk, bk,
        nullptr, nullptr, nullptr, nullptr, nullptr, pK, DIMH, M, DIMH);
    gemm_kernel<false, false, 0><<<g1, 256>>>(x, DIMH, Wv, bv,
        nullptr, nullptr, nullptr, nullptr, nullptr, pV, DIMH, M, DIMH);

    // edge attention
    int eBlocks = (E * 8 + 255) / 256;
    edge_exp_kernel<<<eBlocks, 256>>>(pK, x, pEi, pEsc, pDen, E);
    edge_msg_kernel<<<eBlocks, 256>>>(pV, pEi, pEsc, pDen, pAgg, E);

    // y = agg @ Wo^T + bo + x
    gemm_kernel<false, false, 1><<<g1, 256>>>(pAgg, DIMH, Wo, bo,
        nullptr, nullptr, x, nullptr, nullptr, pY, DIMH, M, DIMH);

    // BN1 stats -> affine
    stats_kernel<<<128, 256>>>(pY, pStats, pStats + 128, M);
    finalize_kernel<<<1, 128>>>(pStats, bn1g, bn1b, pAff, pAff + 128, 1.0f / (float)M);

    // z = relu(BN1(y) @ W1^T + b1)   (BN applied on A-load)
    gemm_kernel<true, true, 0><<<g2, 256>>>(pY, DIMH, W1, b1,
        pAff, pAff + 128, nullptr, nullptr, nullptr, pZ, 2 * DIMH, M, DIMH);

    // t2 = z @ W2^T + b2 + BN1(y)   (residual with affine) -> d_out
    gemm_kernel<false, false, 2><<<g1, 256>>>(pZ, 2 * DIMH, W2, b2,
        nullptr, nullptr, pY, pAff, pAff + 128, out, DIMH, M, 2 * DIMH);

    // BN2 stats -> affine -> apply in place
    stats_kernel<<<128, 256>>>(out, pStats + 256, pStats + 384, M);
    finalize_kernel<<<1, 128>>>(pStats + 256, bn2g, bn2b, pAff + 256, pAff + 384,
                                1.0f / (float)M);
    bn_apply_kernel<<<(M * 32 + 255) / 256, 256>>>(out, pAff + 256, pAff + 384, M * 32);
}

// round 12
// speedup vs baseline: 1.2102x; 1.2102x over previous
#include <cuda_runtime.h>
#include <cuda_bf16.h>
#include <math.h>
#include <stdint.h>

// Problem constants (fixed by the dataset; scratch sized for them)
#define DIMH   128
#define MAXN   40000
#define MAXE   640000

// ---------------- device scratch (no runtime allocation allowed) ----------------
__device__ float g_K[MAXN * DIMH];
__device__ float g_V[MAXN * DIMH];
__device__ float g_agg[MAXN * DIMH];
__device__ float g_y[MAXN * DIMH];
__device__ float g_z[MAXN * 2 * DIMH];
__device__ float g_escore[MAXE * 8];
__device__ float g_denom[MAXN * 8];
__device__ int   g_ei[2 * MAXE];     // normalized int32 edge indices
__device__ int   g_idx64;            // 1 if input edge_index is int64
__device__ float g_stats[512];
__device__ float g_aff[512];

// ---------------- helpers ----------------
__device__ __forceinline__ void red_add_v4(float* p, float4 v) {
    asm volatile("red.global.add.v4.f32 [%0], {%1, %2, %3, %4};"
                 :: "l"(p), "f"(v.x), "f"(v.y), "f"(v.z), "f"(v.w) : "memory");
}

// bf16 mma.sync (sm_80 baseline PTX -> fallback HMMA on sm_103)
__device__ __forceinline__ void mma_bf16(float* c, const uint32_t* a, const uint32_t* b) {
    asm volatile(
        "mma.sync.aligned.m16n8k16.row.col.f32.bf16.bf16.f32 "
        "{%0,%1,%2,%3}, {%4,%5,%6,%7}, {%8,%9}, {%0,%1,%2,%3};"
        : "+f"(c[0]), "+f"(c[1]), "+f"(c[2]), "+f"(c[3])
        : "r"(a[0]), "r"(a[1]), "r"(a[2]), "r"(a[3]), "r"(b[0]), "r"(b[1]));
}

// split v into bf16 hi + bf16 lo (error-compensated product needs hi*hi+hi*lo+lo*hi)
__device__ __forceinline__ void split2(float x, float y, uint32_t& hi, uint32_t& lo) {
    __nv_bfloat16 hx = __float2bfloat16(x);
    __nv_bfloat16 hy = __float2bfloat16(y);
    float rx = x - __bfloat162float(hx);
    float ry = y - __bfloat162float(hy);
    __nv_bfloat162 h2 = __halves2bfloat162(hx, hy);        // x -> low half
    __nv_bfloat162 l2 = __floats2bfloat162_rn(rx, ry);
    hi = *reinterpret_cast<uint32_t*>(&h2);
    lo = *reinterpret_cast<uint32_t*>(&l2);
}

// ================= edge_index dtype detection + normalization =================
__global__ void detect_idx_kernel(const unsigned long long* p) {
    __shared__ int big;
    if (threadIdx.x == 0) big = 0;
    __syncthreads();
    unsigned long long v = p[threadIdx.x];
    if (v >= (1ULL << 32)) atomicOr(&big, 1);
    __syncthreads();
    if (threadIdx.x == 0) g_idx64 = big ? 0 : 1;
}
__global__ void convert_idx_kernel(const void* p, int* out, int n) {
    int i = blockIdx.x * blockDim.x + threadIdx.x;
    if (i >= n) return;
    if (g_idx64) out[i] = (int)((const long long*)p)[i];
    else         out[i] = ((const int*)p)[i];
}

// ================= init =================
__global__ void init_kernel(float* agg, float* denom, float* stats, int nAgg, int nDen) {
    int i = blockIdx.x * blockDim.x + threadIdx.x;
    if (i < nAgg) agg[i] = 0.f;
    if (i < nDen) denom[i] = 0.f;
    if (i < 512)  stats[i] = 0.f;
}

// ================= bf16-split HMMA GEMM =================
// C[M,N] = A[M,K] @ B[N,K]^T + bias (+ epilogue). CTA tile 128x128, K chunk 32.
// 8 warps: warp tile 32(m) x 64(n); mma tiles 2(m) x 8(n) of m16n8k16.
// AAFF: per-K-column affine on A load (fused BN). RES: 0 none, 1 +=res, 2 +=res*rs+rh.
template<bool AAFF, bool RELU, int RES>
__global__ __launch_bounds__(256, 1)
void mma_gemm(const float* __restrict__ A, int lda,
              const float* __restrict__ B,     // [Ntot, K] row-major
              const float* __restrict__ bias,
              const float* __restrict__ ascale, const float* __restrict__ ashift,
              const float* __restrict__ res,
              const float* __restrict__ rscale, const float* __restrict__ rshift,
              float* __restrict__ C, int ldc,
              int M, int K)
{
    // k-pairs: 32 floats per chunk = 16 u32 kpairs; stride 18 to dodge bank conflicts
    __shared__ uint32_t Ah[128][18], Al[128][18], Bh[128][18], Bl[128][18];

    const int tid = threadIdx.x;
    const int wid = tid >> 5;
    const int lid = tid & 31;
    const int gid = lid >> 2;      // 0..7  (row-in-8 group)
    const int tig = lid & 3;       // 0..3  (kpair lane)
    const int bm0 = blockIdx.x * 128;
    const int bn0 = blockIdx.y * 128;
    const int wm0 = (wid & 3) * 32;
    const int wn0 = (wid >> 2) * 64;
    const float* Bp = B + (size_t)bn0 * K;

    float acc[2][8][4];
#pragma unroll
    for (int i = 0; i < 2; i++)
#pragma unroll
        for (int j = 0; j < 8; j++)
#pragma unroll
            for (int q = 0; q < 4; q++) acc[i][j][q] = 0.f;

    for (int kk = 0; kk < K; kk += 32) {
        // ---- load + split A chunk (128 rows x 32 cols) ----
#pragma unroll
        for (int it = 0; it < 4; it++) {
            int lin = tid + it * 256;
            int row = lin >> 3, q = lin & 7;           // q: float4 index (0..7)
            float4 v = make_float4(0.f, 0.f, 0.f, 0.f);
            if (bm0 + row < M)
                v = *reinterpret_cast<const float4*>(A + (size_t)(bm0 + row) * lda + kk + q * 4);
            if (AAFF) {
                int c = kk + q * 4;
                v.x = v.x * ascale[c + 0] + ashift[c + 0];
                v.y = v.y * ascale[c + 1] + ashift[c + 1];
                v.z = v.z * ascale[c + 2] + ashift[c + 2];
                v.w = v.w * ascale[c + 3] + ashift[c + 3];
            }
            uint32_t h0, l0, h1, l1;
            split2(v.x, v.y, h0, l0);
            split2(v.z, v.w, h1, l1);
            Ah[row][q * 2] = h0; Ah[row][q * 2 + 1] = h1;
            Al[row][q * 2] = l0; Al[row][q * 2 + 1] = l1;
        }
        // ---- load + split B chunk (128 rows x 32 cols), always in-range ----
#pragma unroll
        for (int it = 0; it < 4; it++) {
            int lin = tid + it * 256;
            int row = lin >> 3, q = lin & 7;
            float4 v = *reinterpret_cast<const float4*>(Bp + (size_t)row * K + kk + q * 4);
            uint32_t h0, l0, h1, l1;
            split2(v.x, v.y, h0, l0);
            split2(v.z, v.w, h1, l1);
            Bh[row][q * 2] = h0; Bh[row][q * 2 + 1] = h1;
            Bl[row][q * 2] = l0; Bl[row][q * 2 + 1] = l1;
        }
        __syncthreads();

        // ---- 2 k16 steps per chunk ----
#pragma unroll
        for (int ks = 0; ks < 2; ks++) {
            const int kp = ks * 8;
            uint32_t ah[2][4], al[2][4];
#pragma unroll
            for (int i = 0; i < 2; i++) {
                int r0 = wm0 + i * 16 + gid;
                ah[i][0] = Ah[r0][kp + tig];     ah[i][1] = Ah[r0 + 8][kp + tig];
                ah[i][2] = Ah[r0][kp + tig + 4]; ah[i][3] = Ah[r0 + 8][kp + tig + 4];
                al[i][0] = Al[r0][kp + tig];     al[i][1] = Al[r0 + 8][kp + tig];
                al[i][2] = Al[r0][kp + tig + 4]; al[i][3] = Al[r0 + 8][kp + tig + 4];
            }
            uint32_t bh[8][2], bl[8][2];
#pragma unroll
            for (int j = 0; j < 8; j++) {
                int rn = wn0 + j * 8 + gid;
                bh[j][0] = Bh[rn][kp + tig]; bh[j][1] = Bh[rn][kp + tig + 4];
                bl[j][0] = Bl[rn][kp + tig]; bl[j][1] = Bl[rn][kp + tig + 4];
            }
#pragma unroll
            for (int i = 0; i < 2; i++)
#pragma unroll
                for (int j = 0; j < 8; j++) {
                    mma_bf16(acc[i][j], ah[i], bh[j]);
                    mma_bf16(acc[i][j], ah[i], bl[j]);
                    mma_bf16(acc[i][j], al[i], bh[j]);
                }
        }
        __syncthreads();
    }

    // ---- epilogue ----
    // thread covers cols: wn0 + j*8 + 2*tig (+1), rows wm0 + i*16 + gid (+8)
#pragma unroll
    for (int i = 0; i < 2; i++) {
#pragma unroll
        for (int half = 0; half < 2; half++) {
            int row = bm0 + wm0 + i * 16 + gid + half * 8;
            if (row >= M) continue;
#pragma unroll
            for (int j = 0; j < 8; j++) {
                int col = bn0 + wn0 + j * 8 + 2 * tig;
                float v0 = acc[i][j][half * 2 + 0] + bias[col];
                float v1 = acc[i][j][half * 2 + 1] + bias[col + 1];
                if (RES >= 1) {
                    float2 q = *reinterpret_cast<const float2*>(res + (size_t)row * ldc + col);
                    if (RES == 1) { v0 += q.x; v1 += q.y; }
                    else {
                        v0 += q.x * rscale[col] + rshift[col];
                        v1 += q.y * rscale[col + 1] + rshift[col + 1];
                    }
                }
                if (RELU) { v0 = fmaxf(v0, 0.f); v1 = fmaxf(v1, 0.f); }
                *reinterpret_cast<float2*>(C + (size_t)row * ldc + col) = make_float2(v0, v1);
            }
        }
    }
}

// ================= edge pass A: e = exp(K[src].Q[dst]/4), denom[dst,h] += e ============
__global__ void edge_exp_kernel(const float* __restrict__ K, const float* __restrict__ Q,
                                const int* __restrict__ ei,
                                float* __restrict__ escore, float* __restrict__ denom, int E)
{
    int t = blockIdx.x * blockDim.x + threadIdx.x;
    if (t >= E * 8) return;
    int e = t >> 3, h = t & 7;
    int src = ei[e];
    int dst = ei[E + e];
    const float4* kr = reinterpret_cast<const float4*>(K + (size_t)src * DIMH + h * 16);
    const float4* qr = reinterpret_cast<const float4*>(Q + (size_t)dst * DIMH + h * 16);
    float s = 0.f;
#pragma unroll
    for (int i = 0; i < 4; i++) {
        float4 a = kr[i], b = qr[i];
        s += a.x * b.x + a.y * b.y + a.z * b.z + a.w * b.w;
    }
    s *= 0.25f;
    float ev = expf(s);
    escore[t] = ev;
    atomicAdd(&denom[dst * 8 + h], ev);
}

// ================= edge pass B: agg[dst] += V[src] * attn =================
__global__ void edge_msg_kernel(const float* __restrict__ V,
                                const int* __restrict__ ei,
                                const float* __restrict__ escore,
                                const float* __restrict__ denom,
                                float* __restrict__ agg, int E)
{
    int t = blockIdx.x * blockDim.x + threadIdx.x;
    if (t >= E * 8) return;
    int e = t >> 3, h = t & 7;
    int src = ei[e];
    int dst = ei[E + e];
    float attn = escore[t] / (denom[dst * 8 + h] + 1e-16f);
    const float4* vr = reinterpret_cast<const float4*>(V + (size_t)src * DIMH + h * 16);
    float* op = agg + (size_t)dst * DIMH + h * 16;
#pragma unroll
    for (int i = 0; i < 4; i++) {
        float4 v = vr[i];
        red_add_v4(op + i * 4, make_float4(v.x * attn, v.y * attn, v.z * attn, v.w * attn));
    }
}

// ================= batchnorm =================
__global__ void stats_kernel(const float* __restrict__ X, float* s1, float* s2, int M)
{
    __shared__ float sa[256], sb[256];
    int col = threadIdx.x & 127;
    int half = threadIdx.x >> 7;
    int per = (M + gridDim.x - 1) / gridDim.x;
    int r0 = blockIdx.x * per;
    int r1 = min(M, r0 + per);
    float a = 0.f, b = 0.f;
    for (int r = r0 + half; r < r1; r += 2) {
        float v = X[(size_t)r * DIMH + col];
        a += v;
        b = fmaf(v, v, b);
    }
    sa[threadIdx.x] = a; sb[threadIdx.x] = b;
    __syncthreads();
    if (half == 0) {
        atomicAdd(&s1[col], a + sa[col + 128]);
        atomicAdd(&s2[col], b + sb[col + 128]);
    }
}

__global__ void finalize_kernel(const float* __restrict__ stats,
                                const float* __restrict__ g, const float* __restrict__ b,
                                float* scale, float* shift, float invN)
{
    int c = threadIdx.x;
    float mu = stats[c] * invN;
    float var = stats[128 + c] * invN - mu * mu;
    float sc = g[c] * rsqrtf(var + 1e-5f);
    scale[c] = sc;
    shift[c] = b[c] - mu * sc;
}

__global__ void bn_apply_kernel(float* io, const float* __restrict__ scale,
                                const float* __restrict__ shift, int n4)
{
    int i = blockIdx.x * blockDim.x + threadIdx.x;
    if (i >= n4) return;
    float4 v = reinterpret_cast<float4*>(io)[i];
    int col = (i & 31) * 4;
    v.x = v.x * scale[col + 0] + shift[col + 0];
    v.y = v.y * scale[col + 1] + shift[col + 1];
    v.z = v.z * scale[col + 2] + shift[col + 2];
    v.w = v.w * scale[col + 3] + shift[col + 3];
    reinterpret_cast<float4*>(io)[i] = v;
}

// ================= launch =================
extern "C" void kernel_launch(void* const* d_in, const int* in_sizes, int n_in,
                              void* d_out, int out_size)
{
    const float* x    = (const float*)d_in[0];
    const void*  eraw = d_in[1];
    const float* Wk   = (const float*)d_in[2];
    const float* bk   = (const float*)d_in[3];
    const float* Wv   = (const float*)d_in[4];
    const float* bv   = (const float*)d_in[5];
    const float* Wo   = (const float*)d_in[6];
    const float* bo   = (const float*)d_in[7];
    const float* bn1g = (const float*)d_in[8];
    const float* bn1b = (const float*)d_in[9];
    const float* W1   = (const float*)d_in[10];
    const float* b1   = (const float*)d_in[11];
    const float* W2   = (const float*)d_in[12];
    const float* b2   = (const float*)d_in[13];
    const float* bn2g = (const float*)d_in[14];
    const float* bn2b = (const float*)d_in[15];
    float* out = (float*)d_out;

    const int M = in_sizes[0] / DIMH;   // 40000
    const int E = in_sizes[1] / 2;      // 640000

    float *pK, *pV, *pAgg, *pY, *pZ, *pEsc, *pDen, *pStats, *pAff;
    int *pEi;
    cudaGetSymbolAddress((void**)&pK,     g_K);
    cudaGetSymbolAddress((void**)&pV,     g_V);
    cudaGetSymbolAddress((void**)&pAgg,   g_agg);
    cudaGetSymbolAddress((void**)&pY,     g_y);
    cudaGetSymbolAddress((void**)&pZ,     g_z);
    cudaGetSymbolAddress((void**)&pEsc,   g_escore);
    cudaGetSymbolAddress((void**)&pDen,   g_denom);
    cudaGetSymbolAddress((void**)&pEi,    g_ei);
    cudaGetSymbolAddress((void**)&pStats, g_stats);
    cudaGetSymbolAddress((void**)&pAff,   g_aff);

    // normalize edge_index dtype (int64 vs int32) into int scratch
    detect_idx_kernel<<<1, 1024>>>((const unsigned long long*)eraw);
    convert_idx_kernel<<<(2 * E + 255) / 256, 256>>>(eraw, pEi, 2 * E);

    const int nAgg = M * DIMH;
    init_kernel<<<(nAgg + 255) / 256, 256>>>(pAgg, pDen, pStats, nAgg, M * 8);

    dim3 g1((M + 127) / 128, 1);
    dim3 g2((M + 127) / 128, 2);

    // K = x @ Wk^T + bk ; V = x @ Wv^T + bv
    mma_gemm<false, false, 0><<<g1, 256>>>(x, DIMH, Wk, bk,
        nullptr, nullptr, nullptr, nullptr, nullptr, pK, DIMH, M, DIMH);
    mma_gemm<false, false, 0><<<g1, 256>>>(x, DIMH, Wv, bv,
        nullptr, nullptr, nullptr, nullptr, nullptr, pV, DIMH, M, DIMH);

    // edge attention
    int eBlocks = (E * 8 + 255) / 256;
    edge_exp_kernel<<<eBlocks, 256>>>(pK, x, pEi, pEsc, pDen, E);
    edge_msg_kernel<<<eBlocks, 256>>>(pV, pEi, pEsc, pDen, pAgg, E);

    // y = agg @ Wo^T + bo + x
    mma_gemm<false, false, 1><<<g1, 256>>>(pAgg, DIMH, Wo, bo,
        nullptr, nullptr, x, nullptr, nullptr, pY, DIMH, M, DIMH);

    // BN1 stats -> affine
    stats_kernel<<<128, 256>>>(pY, pStats, pStats + 128, M);
    finalize_kernel<<<1, 128>>>(pStats, bn1g, bn1b, pAff, pAff + 128, 1.0f / (float)M);

    // z = relu(BN1(y) @ W1^T + b1)   (BN applied on A-load), N=256 via grid.y=2
    mma_gemm<true, true, 0><<<g2, 256>>>(pY, DIMH, W1, b1,
        pAff, pAff + 128, nullptr, nullptr, nullptr, pZ, 2 * DIMH, M, DIMH);

    // out = z @ W2^T + b2 + BN1(y)   (residual with affine)
    mma_gemm<false, false, 2><<<g1, 256>>>(pZ, 2 * DIMH, W2, b2,
        nullptr, nullptr, pY, pAff, pAff + 128, out, DIMH, M, 2 * DIMH);

    // BN2 stats -> affine -> apply in place
    stats_kernel<<<128, 256>>>(out, pStats + 256, pStats + 384, M);
    finalize_kernel<<<1, 128>>>(pStats + 256, bn2g, bn2b, pAff + 256, pAff + 384,
                                1.0f / (float)M);
    bn_apply_kernel<<<(M * 32 + 255) / 256, 256>>>(out, pAff + 256, pAff + 384, M * 32);
}

// round 13
// speedup vs baseline: 1.2127x; 1.0021x over previous
#include <cuda_runtime.h>
#include <cuda_bf16.h>
#include <math.h>
#include <stdint.h>

// Problem constants (fixed by the dataset; scratch sized for them)
#define DIMH   128
#define MAXN   40000
#define MAXE   640000

// ---------------- device scratch (no runtime allocation allowed) ----------------
__device__ float g_K[MAXN * DIMH];
__device__ float g_V[MAXN * DIMH];
__device__ float g_agg[MAXN * DIMH];
__device__ float g_y[MAXN * DIMH];
__device__ float g_z[MAXN * 2 * DIMH];
__device__ float g_escore[MAXE * 8];
__device__ float g_denom[MAXN * 8];
__device__ int   g_ei[2 * MAXE];     // normalized int32 edge indices
__device__ int   g_idx64;            // 1 if input edge_index is int64
__device__ float g_stats[512];
__device__ float g_aff[512];

// ---------------- helpers ----------------
__device__ __forceinline__ void red_add_v4(float* p, float4 v) {
    asm volatile("red.global.add.v4.f32 [%0], {%1, %2, %3, %4};"
                 :: "l"(p), "f"(v.x), "f"(v.y), "f"(v.z), "f"(v.w) : "memory");
}

// bf16 mma.sync (sm_80 baseline PTX -> fallback HMMA on sm_103)
__device__ __forceinline__ void mma_bf16(float* c, const uint32_t* a, const uint32_t* b) {
    asm volatile(
        "mma.sync.aligned.m16n8k16.row.col.f32.bf16.bf16.f32 "
        "{%0,%1,%2,%3}, {%4,%5,%6,%7}, {%8,%9}, {%0,%1,%2,%3};"
        : "+f"(c[0]), "+f"(c[1]), "+f"(c[2]), "+f"(c[3])
        : "r"(a[0]), "r"(a[1]), "r"(a[2]), "r"(a[3]), "r"(b[0]), "r"(b[1]));
}

// split v into bf16 hi + bf16 lo (error-compensated product needs hi*hi+hi*lo+lo*hi)
__device__ __forceinline__ void split2(float x, float y, uint32_t& hi, uint32_t& lo) {
    __nv_bfloat16 hx = __float2bfloat16(x);
    __nv_bfloat16 hy = __float2bfloat16(y);
    float rx = x - __bfloat162float(hx);
    float ry = y - __bfloat162float(hy);
    __nv_bfloat162 h2 = __halves2bfloat162(hx, hy);        // x -> low half
    __nv_bfloat162 l2 = __floats2bfloat162_rn(rx, ry);
    hi = *reinterpret_cast<uint32_t*>(&h2);
    lo = *reinterpret_cast<uint32_t*>(&l2);
}

// ================= edge_index dtype detection + normalization =================
__global__ void detect_idx_kernel(const unsigned long long* p) {
    __shared__ int big;
    if (threadIdx.x == 0) big = 0;
    __syncthreads();
    unsigned long long v = p[threadIdx.x];
    if (v >= (1ULL << 32)) atomicOr(&big, 1);
    __syncthreads();
    if (threadIdx.x == 0) g_idx64 = big ? 0 : 1;
}
__global__ void convert_idx_kernel(const void* p, int* out, int n) {
    int i = blockIdx.x * blockDim.x + threadIdx.x;
    if (i >= n) return;
    if (g_idx64) out[i] = (int)((const long long*)p)[i];
    else         out[i] = ((const int*)p)[i];
}

// ================= init =================
__global__ void init_kernel(float* agg, float* denom, float* stats, int nAgg, int nDen) {
    int i = blockIdx.x * blockDim.x + threadIdx.x;
    if (i < nAgg) agg[i] = 0.f;
    if (i < nDen) denom[i] = 0.f;
    if (i < 512)  stats[i] = 0.f;
}

// ================= bf16-split HMMA GEMM =================
// C[M,N] = A[M,K] @ B[N,K]^T + bias (+ epilogue). CTA tile 128x128, K chunk 32.
// 8 warps: warp tile 32(m) x 64(n); mma tiles 2(m) x 8(n) of m16n8k16.
// AAFF: per-K-column affine on A load (fused BN). RES: 0 none, 1 +=res, 2 +=res*rs+rh.
template<bool AAFF, bool RELU, int RES>
__global__ __launch_bounds__(256, 1)
void mma_gemm(const float* __restrict__ A, int lda,
              const float* __restrict__ B,     // [Ntot, K] row-major
              const float* __restrict__ bias,
              const float* __restrict__ ascale, const float* __restrict__ ashift,
              const float* __restrict__ res,
              const float* __restrict__ rscale, const float* __restrict__ rshift,
              float* __restrict__ C, int ldc,
              int M, int K)
{
    // k-pairs: 32 floats per chunk = 16 u32 kpairs; stride 18 to dodge bank conflicts
    __shared__ uint32_t Ah[128][18], Al[128][18], Bh[128][18], Bl[128][18];

    const int tid = threadIdx.x;
    const int wid = tid >> 5;
    const int lid = tid & 31;
    const int gid = lid >> 2;      // 0..7  (row-in-8 group)
    const int tig = lid & 3;       // 0..3  (kpair lane)
    const int bm0 = blockIdx.x * 128;
    const int bn0 = blockIdx.y * 128;
    const int wm0 = (wid & 3) * 32;
    const int wn0 = (wid >> 2) * 64;
    const float* Bp = B + (size_t)bn0 * K;

    float acc[2][8][4];
#pragma unroll
    for (int i = 0; i < 2; i++)
#pragma unroll
        for (int j = 0; j < 8; j++)
#pragma unroll
            for (int q = 0; q < 4; q++) acc[i][j][q] = 0.f;

    for (int kk = 0; kk < K; kk += 32) {
        // ---- load + split A chunk (128 rows x 32 cols) ----
#pragma unroll
        for (int it = 0; it < 4; it++) {
            int lin = tid + it * 256;
            int row = lin >> 3, q = lin & 7;           // q: float4 index (0..7)
            float4 v = make_float4(0.f, 0.f, 0.f, 0.f);
            if (bm0 + row < M)
                v = *reinterpret_cast<const float4*>(A + (size_t)(bm0 + row) * lda + kk + q * 4);
            if (AAFF) {
                int c = kk + q * 4;
                v.x = v.x * ascale[c + 0] + ashift[c + 0];
                v.y = v.y * ascale[c + 1] + ashift[c + 1];
                v.z = v.z * ascale[c + 2] + ashift[c + 2];
                v.w = v.w * ascale[c + 3] + ashift[c + 3];
            }
            uint32_t h0, l0, h1, l1;
            split2(v.x, v.y, h0, l0);
            split2(v.z, v.w, h1, l1);
            Ah[row][q * 2] = h0; Ah[row][q * 2 + 1] = h1;
            Al[row][q * 2] = l0; Al[row][q * 2 + 1] = l1;
        }
        // ---- load + split B chunk (128 rows x 32 cols), always in-range ----
#pragma unroll
        for (int it = 0; it < 4; it++) {
            int lin = tid + it * 256;
            int row = lin >> 3, q = lin & 7;
            float4 v = *reinterpret_cast<const float4*>(Bp + (size_t)row * K + kk + q * 4);
            uint32_t h0, l0, h1, l1;
            split2(v.x, v.y, h0, l0);
            split2(v.z, v.w, h1, l1);
            Bh[row][q * 2] = h0; Bh[row][q * 2 + 1] = h1;
            Bl[row][q * 2] = l0; Bl[row][q * 2 + 1] = l1;
        }
        __syncthreads();

        // ---- 2 k16 steps per chunk ----
#pragma unroll
        for (int ks = 0; ks < 2; ks++) {
            const int kp = ks * 8;
            uint32_t ah[2][4], al[2][4];
#pragma unroll
            for (int i = 0; i < 2; i++) {
                int r0 = wm0 + i * 16 + gid;
                ah[i][0] = Ah[r0][kp + tig];     ah[i][1] = Ah[r0 + 8][kp + tig];
                ah[i][2] = Ah[r0][kp + tig + 4]; ah[i][3] = Ah[r0 + 8][kp + tig + 4];
                al[i][0] = Al[r0][kp + tig];     al[i][1] = Al[r0 + 8][kp + tig];
                al[i][2] = Al[r0][kp + tig + 4]; al[i][3] = Al[r0 + 8][kp + tig + 4];
            }
            uint32_t bh[8][2], bl[8][2];
#pragma unroll
            for (int j = 0; j < 8; j++) {
                int rn = wn0 + j * 8 + gid;
                bh[j][0] = Bh[rn][kp + tig]; bh[j][1] = Bh[rn][kp + tig + 4];
                bl[j][0] = Bl[rn][kp + tig]; bl[j][1] = Bl[rn][kp + tig + 4];
            }
#pragma unroll
            for (int i = 0; i < 2; i++)
#pragma unroll
                for (int j = 0; j < 8; j++) {
                    mma_bf16(acc[i][j], ah[i], bh[j]);
                    mma_bf16(acc[i][j], ah[i], bl[j]);
                    mma_bf16(acc[i][j], al[i], bh[j]);
                }
        }
        __syncthreads();
    }

    // ---- epilogue ----
    // thread covers cols: wn0 + j*8 + 2*tig (+1), rows wm0 + i*16 + gid (+8)
#pragma unroll
    for (int i = 0; i < 2; i++) {
#pragma unroll
        for (int half = 0; half < 2; half++) {
            int row = bm0 + wm0 + i * 16 + gid + half * 8;
            if (row >= M) continue;
#pragma unroll
            for (int j = 0; j < 8; j++) {
                int col = bn0 + wn0 + j * 8 + 2 * tig;
                float v0 = acc[i][j][half * 2 + 0] + bias[col];
                float v1 = acc[i][j][half * 2 + 1] + bias[col + 1];
                if (RES >= 1) {
                    float2 q = *reinterpret_cast<const float2*>(res + (size_t)row * ldc + col);
                    if (RES == 1) { v0 += q.x; v1 += q.y; }
                    else {
                        v0 += q.x * rscale[col] + rshift[col];
                        v1 += q.y * rscale[col + 1] + rshift[col + 1];
                    }
                }
                if (RELU) { v0 = fmaxf(v0, 0.f); v1 = fmaxf(v1, 0.f); }
                *reinterpret_cast<float2*>(C + (size_t)row * ldc + col) = make_float2(v0, v1);
            }
        }
    }
}

// ================= edge pass A: e = exp(K[src].Q[dst]/4), denom[dst,h] += e ============
__global__ void edge_exp_kernel(const float* __restrict__ K, const float* __restrict__ Q,
                                const int* __restrict__ ei,
                                float* __restrict__ escore, float* __restrict__ denom, int E)
{
    int t = blockIdx.x * blockDim.x + threadIdx.x;
    if (t >= E * 8) return;
    int e = t >> 3, h = t & 7;
    int src = ei[e];
    int dst = ei[E + e];
    const float4* kr = reinterpret_cast<const float4*>(K + (size_t)src * DIMH + h * 16);
    const float4* qr = reinterpret_cast<const float4*>(Q + (size_t)dst * DIMH + h * 16);
    float s = 0.f;
#pragma unroll
    for (int i = 0; i < 4; i++) {
        float4 a = kr[i], b = qr[i];
        s += a.x * b.x + a.y * b.y + a.z * b.z + a.w * b.w;
    }
    s *= 0.25f;
    float ev = expf(s);
    escore[t] = ev;
    atomicAdd(&denom[dst * 8 + h], ev);
}

// ================= edge pass B: agg[dst] += V[src] * attn =================
__global__ void edge_msg_kernel(const float* __restrict__ V,
                                const int* __restrict__ ei,
                                const float* __restrict__ escore,
                                const float* __restrict__ denom,
                                float* __restrict__ agg, int E)
{
    int t = blockIdx.x * blockDim.x + threadIdx.x;
    if (t >= E * 8) return;
    int e = t >> 3, h = t & 7;
    int src = ei[e];
    int dst = ei[E + e];
    float attn = escore[t] / (denom[dst * 8 + h] + 1e-16f);
    const float4* vr = reinterpret_cast<const float4*>(V + (size_t)src * DIMH + h * 16);
    float* op = agg + (size_t)dst * DIMH + h * 16;
#pragma unroll
    for (int i = 0; i < 4; i++) {
        float4 v = vr[i];
        red_add_v4(op + i * 4, make_float4(v.x * attn, v.y * attn, v.z * attn, v.w * attn));
    }
}

// ================= batchnorm =================
__global__ void stats_kernel(const float* __restrict__ X, float* s1, float* s2, int M)
{
    __shared__ float sa[256], sb[256];
    int col = threadIdx.x & 127;
    int half = threadIdx.x >> 7;
    int per = (M + gridDim.x - 1) / gridDim.x;
    int r0 = blockIdx.x * per;
    int r1 = min(M, r0 + per);
    float a = 0.f, b = 0.f;
    for (int r = r0 + half; r < r1; r += 2) {
        float v = X[(size_t)r * DIMH + col];
        a += v;
        b = fmaf(v, v, b);
    }
    sa[threadIdx.x] = a; sb[threadIdx.x] = b;
    __syncthreads();
    if (half == 0) {
        atomicAdd(&s1[col], a + sa[col + 128]);
        atomicAdd(&s2[col], b + sb[col + 128]);
    }
}

__global__ void finalize_kernel(const float* __restrict__ stats,
                                const float* __restrict__ g, const float* __restrict__ b,
                                float* scale, float* shift, float invN)
{
    int c = threadIdx.x;
    float mu = stats[c] * invN;
    float var = stats[128 + c] * invN - mu * mu;
    float sc = g[c] * rsqrtf(var + 1e-5f);
    scale[c] = sc;
    shift[c] = b[c] - mu * sc;
}

__global__ void bn_apply_kernel(float* io, const float* __restrict__ scale,
                                const float* __restrict__ shift, int n4)
{
    int i = blockIdx.x * blockDim.x + threadIdx.x;
    if (i >= n4) return;
    float4 v = reinterpret_cast<float4*>(io)[i];
    int col = (i & 31) * 4;
    v.x = v.x * scale[col + 0] + shift[col + 0];
    v.y = v.y * scale[col + 1] + shift[col + 1];
    v.z = v.z * scale[col + 2] + shift[col + 2];
    v.w = v.w * scale[col + 3] + shift[col + 3];
    reinterpret_cast<float4*>(io)[i] = v;
}

// ================= launch =================
extern "C" void kernel_launch(void* const* d_in, const int* in_sizes, int n_in,
                              void* d_out, int out_size)
{
    const float* x    = (const float*)d_in[0];
    const void*  eraw = d_in[1];
    const float* Wk   = (const float*)d_in[2];
    const float* bk   = (const float*)d_in[3];
    const float* Wv   = (const float*)d_in[4];
    const float* bv   = (const float*)d_in[5];
    const float* Wo   = (const float*)d_in[6];
    const float* bo   = (const float*)d_in[7];
    const float* bn1g = (const float*)d_in[8];
    const float* bn1b = (const float*)d_in[9];
    const float* W1   = (const float*)d_in[10];
    const float* b1   = (const float*)d_in[11];
    const float* W2   = (const float*)d_in[12];
    const float* b2   = (const float*)d_in[13];
    const float* bn2g = (const float*)d_in[14];
    const float* bn2b = (const float*)d_in[15];
    float* out = (float*)d_out;

    const int M = in_sizes[0] / DIMH;   // 40000
    const int E = in_sizes[1] / 2;      // 640000

    float *pK, *pV, *pAgg, *pY, *pZ, *pEsc, *pDen, *pStats, *pAff;
    int *pEi;
    cudaGetSymbolAddress((void**)&pK,     g_K);
    cudaGetSymbolAddress((void**)&pV,     g_V);
    cudaGetSymbolAddress((void**)&pAgg,   g_agg);
    cudaGetSymbolAddress((void**)&pY,     g_y);
    cudaGetSymbolAddress((void**)&pZ,     g_z);
    cudaGetSymbolAddress((void**)&pEsc,   g_escore);
    cudaGetSymbolAddress((void**)&pDen,   g_denom);
    cudaGetSymbolAddress((void**)&pEi,    g_ei);
    cudaGetSymbolAddress((void**)&pStats, g_stats);
    cudaGetSymbolAddress((void**)&pAff,   g_aff);

    // normalize edge_index dtype (int64 vs int32) into int scratch
    detect_idx_kernel<<<1, 1024>>>((const unsigned long long*)eraw);
    convert_idx_kernel<<<(2 * E + 255) / 256, 256>>>(eraw, pEi, 2 * E);

    const int nAgg = M * DIMH;
    init_kernel<<<(nAgg + 255) / 256, 256>>>(pAgg, pDen, pStats, nAgg, M * 8);

    dim3 g1((M + 127) / 128, 1);
    dim3 g2((M + 127) / 128, 2);

    // K = x @ Wk^T + bk ; V = x @ Wv^T + bv
    mma_gemm<false, false, 0><<<g1, 256>>>(x, DIMH, Wk, bk,
        nullptr, nullptr, nullptr, nullptr, nullptr, pK, DIMH, M, DIMH);
    mma_gemm<false, false, 0><<<g1, 256>>>(x, DIMH, Wv, bv,
        nullptr, nullptr, nullptr, nullptr, nullptr, pV, DIMH, M, DIMH);

    // edge attention
    int eBlocks = (E * 8 + 255) / 256;
    edge_exp_kernel<<<eBlocks, 256>>>(pK, x, pEi, pEsc, pDen, E);
    edge_msg_kernel<<<eBlocks, 256>>>(pV, pEi, pEsc, pDen, pAgg, E);

    // y = agg @ Wo^T + bo + x
    mma_gemm<false, false, 1><<<g1, 256>>>(pAgg, DIMH, Wo, bo,
        nullptr, nullptr, x, nullptr, nullptr, pY, DIMH, M, DIMH);

    // BN1 stats -> affine
    stats_kernel<<<128, 256>>>(pY, pStats, pStats + 128, M);
    finalize_kernel<<<1, 128>>>(pStats, bn1g, bn1b, pAff, pAff + 128, 1.0f / (float)M);

    // z = relu(BN1(y) @ W1^T + b1)   (BN applied on A-load), N=256 via grid.y=2
    mma_gemm<true, true, 0><<<g2, 256>>>(pY, DIMH, W1, b1,
        pAff, pAff + 128, nullptr, nullptr, nullptr, pZ, 2 * DIMH, M, DIMH);

    // out = z @ W2^T + b2 + BN1(y)   (residual with affine)
    mma_gemm<false, false, 2><<<g1, 256>>>(pZ, 2 * DIMH, W2, b2,
        nullptr, nullptr, pY, pAff, pAff + 128, out, DIMH, M, 2 * DIMH);

    // BN2 stats -> affine -> apply in place
    stats_kernel<<<128, 256>>>(out, pStats + 256, pStats + 384, M);
    finalize_kernel<<<1, 128>>>(pStats + 256, bn2g, bn2b, pAff + 256, pAff + 384,
                                1.0f / (float)M);
    bn_apply_kernel<<<(M * 32 + 255) / 256, 256>>>(out, pAff + 256, pAff + 384, M * 32);
}